// round 12
// baseline (speedup 1.0000x reference)
#include <cuda_runtime.h>
#include <cuda_bf16.h>
#include <cuda_fp8.h>
#include <cstdint>
#include <cstddef>

#define N_NODES 4096
#define PSTEPS 10
#define MT 32                    /* rows per CTA */
#define KC 256                   /* k-bytes per stage */
#define NKT 16                   /* 4096/256 */
#define ASTG (MT*KC)             /* 8192  */
#define BSTG (128*KC)            /* 32768 */
#define STG (ASTG+BSTG)          /* 40960 */
#define NIT 48                   /* 3 e * 16 kt */
#define ASCALE 4096.0f
#define INV_ASCALE (1.0f/4096.0f)

/* smem float offsets (from 1024-aligned base) */
#define OFF_PART 0               /* float[3][32][128] = 12288 f (48KB)      */
#define OFF_ZTB  49152           /* BYTE offset: uint8[384][32] = 12KB      */
#define OFF_DW   30720           /* stages end at 122880 B; dw 8192 f       */
#define OFF_CW   38912           /* 1280 f */
#define OFF_WIN  40192           /* 64*20 = 1280 f */
#define OFF_X    41472           /* 8*128 = 1024 f */
#define OFF_OW   42496           /* 256 f */
#define OFF_DB   42752
#define OFF_CB   42816
#define OFF_OB   42880
#define DSM_BYTES (42896*4 + 1024)

// ---------------- device scratch -------------------------------------------
__device__ float g_window[2*N_NODES*20];           // [B][N][T*D]
__device__ float g_pre[3*2*N_NODES*64];            // [E][B*N][H]
__device__ float g_mask[N_NODES];
__device__ float g_cwAll[6*20*64];                 // combined conv@W weights
__device__ float g_bAll[6*64];                     // combined biases
__device__ uint8_t g_Ztf8[3UL*128*4096];           // [E][b*64+h][m] fp8 e4m3
__device__ uint8_t g_adjf8[3UL*4096*4096];         // fp8 e4m3 adjacency * 4096

// ---------------- helpers ---------------------------------------------------
__device__ __forceinline__ uint32_t smem_u32(const void* p) {
    uint32_t a;
    asm("{ .reg .u64 t; cvta.to.shared.u64 t, %1; cvt.u32.u64 %0, t; }" : "=r"(a) : "l"(p));
    return a;
}
__device__ __forceinline__ void ldm4(uint32_t& r0, uint32_t& r1, uint32_t& r2,
                                     uint32_t& r3, uint32_t a) {
    asm volatile("ldmatrix.sync.aligned.m8n8.x4.shared.b16 {%0,%1,%2,%3}, [%4];"
                 : "=r"(r0), "=r"(r1), "=r"(r2), "=r"(r3) : "r"(a));
}
__device__ __forceinline__ void mma16832f8(float* c, const uint32_t* a,
                                           uint32_t b0, uint32_t b1) {
    asm volatile(
        "mma.sync.aligned.m16n8k32.row.col.f32.e4m3.e4m3.f32 "
        "{%0,%1,%2,%3}, {%4,%5,%6,%7}, {%8,%9}, {%0,%1,%2,%3};"
        : "+f"(c[0]), "+f"(c[1]), "+f"(c[2]), "+f"(c[3])
        : "r"(a[0]), "r"(a[1]), "r"(a[2]), "r"(a[3]), "r"(b0), "r"(b1));
}

// ---------------- init kernels ---------------------------------------------
__global__ void k_init_window(const float* __restrict__ ts) {
    int idx = blockIdx.x * 256 + threadIdx.x;      // 163840 total
    int d = idx & 3;
    int r = idx >> 2;
    int t = r % 5;
    int bn = r / 5;
    int n = bn & (N_NODES - 1);
    int b = bn >> 12;
    g_window[idx] = ts[(((size_t)(b*5 + t))*N_NODES + n)*4 + d];
}

__global__ void k_mask(const float* __restrict__ adjs) {
    int m = blockIdx.x * 256 + threadIdx.x;
    float v = 0.f;
    for (size_t i = m; i < (size_t)3*N_NODES*N_NODES; i += N_NODES) {
        if (adjs[i] > 0.f) { v = 1.f; break; }
    }
    g_mask[m] = v;
}

__global__ void k_convA(const float* __restrict__ adjs) {
    size_t i = ((size_t)blockIdx.x * 256 + threadIdx.x) * 8;
    float4 a = *(const float4*)(adjs + i);
    float4 b = *(const float4*)(adjs + i + 4);
    __nv_fp8x4_e4m3 lo(make_float4(a.x*ASCALE, a.y*ASCALE, a.z*ASCALE, a.w*ASCALE));
    __nv_fp8x4_e4m3 hi(make_float4(b.x*ASCALE, b.y*ASCALE, b.z*ASCALE, b.w*ASCALE));
    uint2 v; v.x = lo.__x; v.y = hi.__x;
    *(uint2*)(g_adjf8 + i) = v;
}

__global__ void k_prepw(const float* __restrict__ cw, const float* __restrict__ cb,
                        const float* __restrict__ w1, const float* __restrict__ w2,
                        const float* __restrict__ encb) {
    int mt = blockIdx.x;
    int row = blockIdx.y;
    int e = (mt < 3) ? mt : mt - 3;
    const float* W = ((mt < 3) ? w1 : w2) + e*64*64;
    int h = threadIdx.x;
    const float* src = (row < 20) ? (cw + row*64) : cb;
    float a = 0.f;
#pragma unroll 8
    for (int f = 0; f < 64; f++) a = fmaf(src[f], W[f*64 + h], a);
    if (row < 20) {
        g_cwAll[(mt*20 + row)*64 + h] = a;
    } else {
        if (mt >= 3) a += encb[e*64 + h];
        g_bAll[mt*64 + h] = a;
    }
}

// ---------------- initial Zt/pre (before step 0) ----------------------------
__global__ __launch_bounds__(256) void k_zpre2() {
    __shared__ float sW[6*20*64];
    __shared__ float sB[6*64];
    __shared__ float sWin[64][21];
    int tid = threadIdx.x;
    int g0 = blockIdx.x * 64;

    for (int q = tid; q < 6*20*64; q += 256) sW[q] = g_cwAll[q];
    for (int q = tid; q < 6*64;    q += 256) sB[q] = g_bAll[q];
    for (int q = tid; q < 64*20;   q += 256)
        sWin[q/20][q%20] = g_window[(size_t)(g0 + q/20)*20 + q%20];
    __syncthreads();

    int tx = tid & 15, ty = tid >> 4;
    int h0 = tx * 4;
    int b  = g0 >> 12;
    int m0 = (g0 & 4095) + ty*4;

#pragma unroll
    for (int mt = 0; mt < 6; mt++) {
        float acc[4][4];
#pragma unroll
        for (int i = 0; i < 4; i++)
#pragma unroll
            for (int j = 0; j < 4; j++) acc[i][j] = sB[mt*64 + h0 + j];
#pragma unroll
        for (int k = 0; k < 20; k++) {
            float4 w = *(float4*)&sW[(mt*20 + k)*64 + h0];
            float wv[4] = {w.x, w.y, w.z, w.w};
#pragma unroll
            for (int i = 0; i < 4; i++) {
                float a = sWin[ty*4 + i][k];
#pragma unroll
                for (int j = 0; j < 4; j++) acc[i][j] = fmaf(a, wv[j], acc[i][j]);
            }
        }
        if (mt < 3) {
#pragma unroll
            for (int j = 0; j < 4; j++) {
                __nv_fp8x4_e4m3 p4(make_float4(acc[0][j], acc[1][j], acc[2][j], acc[3][j]));
                *(uint32_t*)(g_Ztf8 + (size_t)(mt*128 + b*64 + h0 + j)*4096 + m0) = p4.__x;
            }
        } else {
            int e = mt - 3;
#pragma unroll
            for (int i = 0; i < 4; i++)
                *(float4*)(g_pre + (size_t)e*(8192*64) + (size_t)(g0 + ty*4 + i)*64 + h0) =
                    make_float4(acc[i][0], acc[i][1], acc[i][2], acc[i][3]);
        }
    }
}

// ---------------- THE fused per-step kernel ---------------------------------
// CTA owns rows [n0, n0+32): 3 GEMM slices (full K) -> smem part -> decode 64
// node-instances -> window shift -> next-step Zt/pre. grid 128 x 256 thr.
__device__ __forceinline__ void issue_it(uint32_t b0, int it, int n0, int tid) {
    uint32_t s = b0 + (uint32_t)(it % 3) * STG;
    const uint8_t* Ae = g_adjf8 + (size_t)(it >> 4) * (4096UL*4096UL);
    const uint8_t* Ze = g_Ztf8  + (size_t)(it >> 4) * (128UL*4096UL);
    int kk = (it & 15) * KC;
#pragma unroll
    for (int k = 0; k < 2; k++) {                  // A: 32 rows x 256B
        int q = tid + k*256;
        int r = q >> 4, c = q & 15;
        int sub = c >> 3, cc = c & 7;
        uint32_t dst = s + (uint32_t)sub*4096 + (uint32_t)r*128
                     + (uint32_t)((cc ^ (r & 7)) << 4);
        const void* g = Ae + (size_t)(n0 + r)*4096 + kk + c*16;
        asm volatile("cp.async.cg.shared.global [%0], [%1], 16;" :: "r"(dst), "l"(g));
    }
#pragma unroll
    for (int k = 0; k < 8; k++) {                  // B: 128 rows x 256B
        int q = tid + k*256;
        int r = q >> 4, c = q & 15;
        int sub = c >> 3, cc = c & 7;
        uint32_t dst = s + ASTG + (uint32_t)sub*16384 + (uint32_t)r*128
                     + (uint32_t)((cc ^ (r & 7)) << 4);
        const void* g = Ze + (size_t)r*4096 + kk + c*16;
        asm volatile("cp.async.cg.shared.global [%0], [%1], 16;" :: "r"(dst), "l"(g));
    }
    asm volatile("cp.async.commit_group;" ::: "memory");
}

__global__ __launch_bounds__(256) void k_step(const float* __restrict__ dw,
                                              const float* __restrict__ db,
                                              const float* __restrict__ ow,
                                              const float* __restrict__ ob,
                                              const float* __restrict__ cw,
                                              const float* __restrict__ cb,
                                              float* __restrict__ outp, int step) {
    extern __shared__ char sm[];
    uint32_t raw = smem_u32(sm);
    uint32_t b0 = (raw + 1023u) & ~1023u;
    float* F = (float*)(sm + (b0 - raw));
    uint8_t* ZTB = (uint8_t*)(sm + (b0 - raw)) + OFF_ZTB;

    const int tid = threadIdx.x;
    const int lane = tid & 31, wid = tid >> 5;
    const int wm = wid & 1, wn = wid >> 1;         // warps 2 x 4, tile 16x32
    const int n0 = blockIdx.x * MT;

    // ---- preamble: weights + windows to smem ----
    for (int q = tid; q < 8192; q += 256) F[OFF_DW + q] = dw[q];
    for (int q = tid; q < 1280; q += 256) F[OFF_CW + q] = cw[q];
    if (tid < 256) F[OFF_OW + tid] = ow[tid];
    if (tid < 64)  F[OFF_DB + tid] = db[tid];
    else if (tid < 128) F[OFF_CB + tid - 64] = cb[tid - 64];
    else if (tid < 132) F[OFF_OB + tid - 128] = ob[tid - 128];
    for (int q = tid; q < 1280; q += 256) {        // 64 nodes x 20
        int nd = q / 20, k = q % 20;
        int b = nd >> 5, r = nd & 31;
        F[OFF_WIN + q] = g_window[(size_t)(b*4096 + n0 + r)*20 + k];
    }

    // ---- GEMM: 3 e-slices, full K, 3-stage pipeline ----
    const int l7 = lane & 7;
    const int rA = wm*16 + l7 + ((lane >> 3) & 1)*8;
    const int klA = lane >> 4;
    const int rB0 = wn*32 + l7 + (lane >> 4)*8;
    const int klB = (lane >> 3) & 1;

    float acc[3][4][4] = {};

    issue_it(b0, 0, n0, tid);
    issue_it(b0, 1, n0, tid);

#pragma unroll
    for (int e = 0; e < 3; e++) {
        for (int kt = 0; kt < NKT; kt++) {
            int it = e*NKT + kt;
            if (e == 2 && kt == NKT-1) asm volatile("cp.async.wait_group 0;" ::: "memory");
            else                       asm volatile("cp.async.wait_group 1;" ::: "memory");
            __syncthreads();
            if (it + 2 < NIT) issue_it(b0, it + 2, n0, tid);

            uint32_t sA = b0 + (uint32_t)(it % 3) * STG;
            uint32_t sB = sA + ASTG;
#pragma unroll
            for (int s4 = 0; s4 < 8; s4++) {
                int sub = s4 >> 2, s2 = s4 & 3;
                uint32_t a[4], b[2][4];
                {
                    uint32_t ad = sA + (uint32_t)sub*4096 + (uint32_t)rA*128
                                + (uint32_t)((((2*s2 + klA) ^ (rA & 7))) << 4);
                    ldm4(a[0], a[1], a[2], a[3], ad);
                }
#pragma unroll
                for (int p = 0; p < 2; p++) {
                    int r = rB0 + p*16;
                    uint32_t bd = sB + (uint32_t)sub*16384 + (uint32_t)r*128
                                + (uint32_t)((((2*s2 + klB) ^ (r & 7))) << 4);
                    ldm4(b[p][0], b[p][1], b[p][2], b[p][3], bd);
                }
#pragma unroll
                for (int nj = 0; nj < 4; nj++) {
                    int p = nj >> 1, hf = nj & 1;
                    mma16832f8(acc[e][nj], a, b[p][hf*2], b[p][hf*2 + 1]);
                }
            }
            __syncthreads();
        }
    }

    // ---- epilogue: acc -> smem part [3][32][128] ----
    {
        const int g8 = lane >> 2, t2 = (lane & 3)*2;
#pragma unroll
        for (int e = 0; e < 3; e++)
#pragma unroll
            for (int nj = 0; nj < 4; nj++) {
                int c = wn*32 + nj*8 + t2;
                int r0 = wm*16 + g8;
                F[OFF_PART + e*4096 + r0*128 + c]       = acc[e][nj][0];
                F[OFF_PART + e*4096 + r0*128 + c + 1]   = acc[e][nj][1];
                F[OFF_PART + e*4096 + (r0+8)*128 + c]   = acc[e][nj][2];
                F[OFF_PART + e*4096 + (r0+8)*128 + c+1] = acc[e][nj][3];
            }
    }
    __syncthreads();

    // ---- decode: 8 warps x 8 rounds = 64 node-instances ----
    for (int round = 0; round < 8; round++) {
        int nd = wid + round*8;
        int b = nd >> 5, r = nd & 31;
        int n = n0 + r, g = b*4096 + n;
        const int c0 = lane, c1 = lane + 32;

        float cv0 = F[OFF_CB + c0], cv1 = F[OFF_CB + c1];
#pragma unroll
        for (int k = 0; k < 20; k++) {
            float wk = F[OFF_WIN + nd*20 + k];
            cv0 = fmaf(wk, F[OFF_CW + k*64 + c0], cv0);
            cv1 = fmaf(wk, F[OFF_CW + k*64 + c1], cv1);
        }
        float ss0 = 0.f, ss1 = 0.f;
#pragma unroll
        for (int e = 0; e < 3; e++) {
            const float* pr = g_pre + (size_t)e*(8192*64) + (size_t)g*64;
            float p0 = F[OFF_PART + e*4096 + r*128 + b*64 + c0] * INV_ASCALE + pr[c0];
            float p1 = F[OFF_PART + e*4096 + r*128 + b*64 + c1] * INV_ASCALE + pr[c1];
            ss0 += tanhf(p0); ss1 += tanhf(p1);
        }
        float mk = g_mask[n];
        F[OFF_X + wid*128 + c0]      = cv0;
        F[OFF_X + wid*128 + c1]      = cv1;
        F[OFF_X + wid*128 + 64 + c0] = tanhf(ss0) * mk;
        F[OFF_X + wid*128 + 96 + c0] = tanhf(ss1) * mk;
        __syncwarp();

        float h0 = F[OFF_DB + c0], h1 = F[OFF_DB + c1];
#pragma unroll 8
        for (int j = 0; j < 128; j++) {
            float xj = F[OFF_X + wid*128 + j];
            h0 = fmaf(xj, F[OFF_DW + j*64 + c0], h0);
            h1 = fmaf(xj, F[OFF_DW + j*64 + c1], h1);
        }
        h0 = fmaxf(h0, 0.f); h1 = fmaxf(h1, 0.f);

        float od[4];
#pragma unroll
        for (int d = 0; d < 4; d++)
            od[d] = h0*F[OFF_OW + c0*4 + d] + h1*F[OFF_OW + c1*4 + d];
#pragma unroll
        for (int off = 16; off; off >>= 1)
#pragma unroll
            for (int d = 0; d < 4; d++)
                od[d] += __shfl_xor_sync(0xffffffffu, od[d], off);

        float nvl = 0.f;
        if (lane < 4) nvl = F[OFF_WIN + nd*20 + 16 + lane] + tanhf(od[lane] + F[OFF_OB + lane]);
        float old4 = (lane < 16) ? F[OFF_WIN + nd*20 + lane + 4] : 0.f;
        float nvs  = __shfl_sync(0xffffffffu, nvl, lane & 3);
        float newv = (lane < 16) ? old4 : nvs;
        __syncwarp();
        if (lane < 20) {
            F[OFF_WIN + nd*20 + lane] = newv;
            g_window[(size_t)g*20 + lane] = newv;
        }
        if (lane < 4)
            outp[(((size_t)b*PSTEPS + step)*4096 + n)*4 + lane] = nvl;
        __syncwarp();
    }
    __syncthreads();

    // ---- zpre: next-step Zt (fp8 staged) + pre (fp32 staged) ----
#pragma unroll
    for (int pass = 0; pass < 2; pass++) {
        int idx = tid + pass*256;
        if (idx < 384) {
            int mt = idx >> 6, h = idx & 63;
            float bias = g_bAll[idx];
            if (mt < 3) {
                for (int nd = 0; nd < 64; nd++) {
                    float a = bias;
#pragma unroll
                    for (int k = 0; k < 20; k++)
                        a = fmaf(F[OFF_WIN + nd*20 + k], g_cwAll[(mt*20 + k)*64 + h], a);
                    int b = nd >> 5, r = nd & 31;
                    __nv_fp8_e4m3 f8(a);
                    ZTB[(mt*128 + b*64 + h)*32 + r] = *(uint8_t*)&f8;
                }
            } else {
                int e = mt - 3;
                for (int nd = 0; nd < 64; nd++) {
                    float a = bias;
#pragma unroll
                    for (int k = 0; k < 20; k++)
                        a = fmaf(F[OFF_WIN + nd*20 + k], g_cwAll[(mt*20 + k)*64 + h], a);
                    F[OFF_PART + nd*192 + e*64 + h] = a;   // part area reused as prebuf
                }
            }
        }
    }
    __syncthreads();

    // Zt writeback: 384 rows x 32B, as 2 uint4 per row
    for (int q = tid; q < 768; q += 256) {
        int row = q >> 1, half = q & 1;
        *(uint4*)(g_Ztf8 + (size_t)row*4096 + n0 + half*16) =
            *(uint4*)(ZTB + row*32 + half*16);
    }
    // pre writeback: warp-per-node, coalesced
    for (int round = 0; round < 8; round++) {
        int nd = wid + round*8;
        int b = nd >> 5, r = nd & 31;
        int g = b*4096 + n0 + r;
        for (int q = lane; q < 192; q += 32)
            g_pre[(size_t)(q >> 6)*(8192*64) + (size_t)g*64 + (q & 63)] =
                F[OFF_PART + nd*192 + q];
    }
}

// ---------------------------------------------------------------------------
extern "C" void kernel_launch(void* const* d_in, const int* in_sizes, int n_in,
                              void* d_out, int out_size) {
    const float* ts   = (const float*)d_in[0];
    const float* adjs = (const float*)d_in[1];
    const float* cw   = (const float*)d_in[2];
    const float* cb   = (const float*)d_in[3];
    const float* w1   = (const float*)d_in[4];
    const float* w2   = (const float*)d_in[5];
    const float* encb = (const float*)d_in[6];
    const float* dw   = (const float*)d_in[7];
    const float* db   = (const float*)d_in[8];
    const float* ow   = (const float*)d_in[9];
    const float* ob   = (const float*)d_in[10];
    float* outp = (float*)d_out;

    cudaFuncSetAttribute(k_step, cudaFuncAttributeMaxDynamicSharedMemorySize, DSM_BYTES);

    k_init_window<<<640, 256>>>(ts);
    k_mask<<<16, 256>>>(adjs);
    k_convA<<<24576, 256>>>(adjs);
    k_prepw<<<dim3(6, 21), 64>>>(cw, cb, w1, w2, encb);
    k_zpre2<<<128, 256>>>();
    for (int p = 0; p < PSTEPS; p++)
        k_step<<<128, 256, DSM_BYTES>>>(dw, db, ow, ob, cw, cb, outp, p);
}

// round 13
// speedup vs baseline: 1.2388x; 1.2388x over previous
#include <cuda_runtime.h>
#include <cuda_bf16.h>
#include <cuda_fp8.h>
#include <cstdint>
#include <cstddef>

#define N_NODES 4096
#define PSTEPS 10
#define NH (N_NODES*64)          /* 262144 */
#define NKI 16                   /* K iterations per CTA: 2048 / 128 (fp8) */
#define STAGE_BYTES 24576        /* A 64x128B (8KB) + B 128x128B (16KB) */
#define DSM_BYTES (3*STAGE_BYTES + 1024)
#define ASCALE 4096.0f
#define INV_ASCALE (1.0f/4096.0f)

/* decpre smem float offsets */
#define OFF_DW4  0               /* [32][64][4] = 8192 f (overlaid by pre-staging later) */
#define OFF_PRE  0               /* [32][192] = 6144 f, reuses DW4 after decode */
#define OFF_CWA  8192            /* 7680 f */
#define OFF_CW   15872           /* 1280 f */
#define OFF_WIN  17152           /* 640 f  */
#define OFF_X    17792           /* 32*128 = 4096 f */
#define OFF_OW   21888           /* 256 f */
#define OFF_DB   22144
#define OFF_CB   22208
#define OFF_OB   22272           /* 8 f */
#define OFF_BALL 22280           /* 384 f -> ends 22664 */
#define ZTB_BYTE 90656           /* 22664*4, 16B aligned; 384*16 = 6144 B */
#define DEC_SMEM_BYTES (ZTB_BYTE + 6144)

// ---------------- device scratch -------------------------------------------
__device__ float g_window[2*N_NODES*20];           // [B][N][T*D]
__device__ float g_pre[3*2*N_NODES*64];            // [E][B*N][H]
__device__ float g_part[12*NH];                    // [S=2][E=3][B=2][N][H]
__device__ float g_mask[N_NODES];
__device__ float g_cwAll[6*20*64];                 // combined conv@W weights
__device__ float g_bAll[6*64];                     // combined biases
__device__ uint8_t g_Ztf8[3UL*128*4096];           // [E][b*64+h][m] fp8 e4m3
__device__ uint8_t g_adjf8[3UL*4096*4096];         // fp8 e4m3 adjacency * 4096

// ---------------- helpers ---------------------------------------------------
__device__ __forceinline__ uint32_t smem_u32(const void* p) {
    uint32_t a;
    asm("{ .reg .u64 t; cvta.to.shared.u64 t, %1; cvt.u32.u64 %0, t; }" : "=r"(a) : "l"(p));
    return a;
}
__device__ __forceinline__ void ldm4(uint32_t& r0, uint32_t& r1, uint32_t& r2,
                                     uint32_t& r3, uint32_t a) {
    asm volatile("ldmatrix.sync.aligned.m8n8.x4.shared.b16 {%0,%1,%2,%3}, [%4];"
                 : "=r"(r0), "=r"(r1), "=r"(r2), "=r"(r3) : "r"(a));
}
__device__ __forceinline__ void mma16832f8(float* c, const uint32_t* a,
                                           uint32_t b0, uint32_t b1) {
    asm volatile(
        "mma.sync.aligned.m16n8k32.row.col.f32.e4m3.e4m3.f32 "
        "{%0,%1,%2,%3}, {%4,%5,%6,%7}, {%8,%9}, {%0,%1,%2,%3};"
        : "+f"(c[0]), "+f"(c[1]), "+f"(c[2]), "+f"(c[3])
        : "r"(a[0]), "r"(a[1]), "r"(a[2]), "r"(a[3]), "r"(b0), "r"(b1));
}

// ---------------- init kernels ---------------------------------------------
__global__ void k_init_window(const float* __restrict__ ts) {
    int idx = blockIdx.x * 256 + threadIdx.x;
    int d = idx & 3;
    int r = idx >> 2;
    int t = r % 5;
    int bn = r / 5;
    int n = bn & (N_NODES - 1);
    int b = bn >> 12;
    g_window[idx] = ts[(((size_t)(b*5 + t))*N_NODES + n)*4 + d];
}

__global__ void k_mask(const float* __restrict__ adjs) {
    int m = blockIdx.x * 256 + threadIdx.x;
    float v = 0.f;
    for (size_t i = m; i < (size_t)3*N_NODES*N_NODES; i += N_NODES) {
        if (adjs[i] > 0.f) { v = 1.f; break; }
    }
    g_mask[m] = v;
}

__global__ void k_convA(const float* __restrict__ adjs) {
    size_t i = ((size_t)blockIdx.x * 256 + threadIdx.x) * 8;
    float4 a = *(const float4*)(adjs + i);
    float4 b = *(const float4*)(adjs + i + 4);
    __nv_fp8x4_e4m3 lo(make_float4(a.x*ASCALE, a.y*ASCALE, a.z*ASCALE, a.w*ASCALE));
    __nv_fp8x4_e4m3 hi(make_float4(b.x*ASCALE, b.y*ASCALE, b.z*ASCALE, b.w*ASCALE));
    uint2 v; v.x = lo.__x; v.y = hi.__x;
    *(uint2*)(g_adjf8 + i) = v;
}

__global__ void k_prepw(const float* __restrict__ cw, const float* __restrict__ cb,
                        const float* __restrict__ w1, const float* __restrict__ w2,
                        const float* __restrict__ encb) {
    int mt = blockIdx.x;
    int row = blockIdx.y;
    int e = (mt < 3) ? mt : mt - 3;
    const float* W = ((mt < 3) ? w1 : w2) + e*64*64;
    int h = threadIdx.x;
    const float* src = (row < 20) ? (cw + row*64) : cb;
    float a = 0.f;
#pragma unroll 8
    for (int f = 0; f < 64; f++) a = fmaf(src[f], W[f*64 + h], a);
    if (row < 20) {
        g_cwAll[(mt*20 + row)*64 + h] = a;
    } else {
        if (mt >= 3) a += encb[e*64 + h];
        g_bAll[mt*64 + h] = a;
    }
}

// ---------------- initial Zt/pre (before step 0) ----------------------------
__global__ __launch_bounds__(256) void k_zpre2() {
    __shared__ float sW[6*20*64];
    __shared__ float sB[6*64];
    __shared__ float sWin[64][21];
    int tid = threadIdx.x;
    int g0 = blockIdx.x * 64;

    for (int q = tid; q < 6*20*64; q += 256) sW[q] = g_cwAll[q];
    for (int q = tid; q < 6*64;    q += 256) sB[q] = g_bAll[q];
    for (int q = tid; q < 64*20;   q += 256)
        sWin[q/20][q%20] = g_window[(size_t)(g0 + q/20)*20 + q%20];
    __syncthreads();

    int tx = tid & 15, ty = tid >> 4;
    int h0 = tx * 4;
    int b  = g0 >> 12;
    int m0 = (g0 & 4095) + ty*4;

#pragma unroll
    for (int mt = 0; mt < 6; mt++) {
        float acc[4][4];
#pragma unroll
        for (int i = 0; i < 4; i++)
#pragma unroll
            for (int j = 0; j < 4; j++) acc[i][j] = sB[mt*64 + h0 + j];
#pragma unroll
        for (int k = 0; k < 20; k++) {
            float4 w = *(float4*)&sW[(mt*20 + k)*64 + h0];
            float wv[4] = {w.x, w.y, w.z, w.w};
#pragma unroll
            for (int i = 0; i < 4; i++) {
                float a = sWin[ty*4 + i][k];
#pragma unroll
                for (int j = 0; j < 4; j++) acc[i][j] = fmaf(a, wv[j], acc[i][j]);
            }
        }
        if (mt < 3) {
#pragma unroll
            for (int j = 0; j < 4; j++) {
                __nv_fp8x4_e4m3 p4(make_float4(acc[0][j], acc[1][j], acc[2][j], acc[3][j]));
                *(uint32_t*)(g_Ztf8 + (size_t)(mt*128 + b*64 + h0 + j)*4096 + m0) = p4.__x;
            }
        } else {
            int e = mt - 3;
#pragma unroll
            for (int i = 0; i < 4; i++)
                *(float4*)(g_pre + (size_t)e*(8192*64) + (size_t)(g0 + ty*4 + i)*64 + h0) =
                    make_float4(acc[i][0], acc[i][1], acc[i][2], acc[i][3]);
        }
    }
}

// ---------------- big GEMM on fp8 mma.sync (unchanged from R10/R11) ----------
__device__ __forceinline__ void issue_tile(uint32_t base, int st,
                                           const uint8_t* Ae,
                                           const uint8_t* Ze,
                                           int n0, int kk, int tid) {
    uint32_t sA = base + (uint32_t)st * STAGE_BYTES;
    uint32_t sB = sA + 8192;
#pragma unroll
    for (int k = 0; k < 2; k++) {
        int q = tid + k*256;
        int r = q >> 3, c = q & 7;
        uint32_t off = (uint32_t)r*128 + (uint32_t)((c ^ (r & 7)) << 4);
        const void* g = Ae + (size_t)(n0 + r)*4096 + kk + c*16;
        asm volatile("cp.async.cg.shared.global [%0], [%1], 16;" :: "r"(sA + off), "l"(g));
    }
#pragma unroll
    for (int k = 0; k < 4; k++) {
        int q = tid + k*256;
        int r = q >> 3, c = q & 7;
        uint32_t off = (uint32_t)r*128 + (uint32_t)((c ^ (r & 7)) << 4);
        const void* g = Ze + (size_t)r*4096 + kk + c*16;
        asm volatile("cp.async.cg.shared.global [%0], [%1], 16;" :: "r"(sB + off), "l"(g));
    }
    asm volatile("cp.async.commit_group;" ::: "memory");
}

__global__ __launch_bounds__(256, 2) void k_bigwmma() {
    extern __shared__ __align__(1024) char dsm[];
    const int tid = threadIdx.x;
    const int lane = tid & 31, wid = tid >> 5;
    const int wm = wid & 1, wn = wid >> 1;
    const int e = blockIdx.y, s = blockIdx.z;
    const int n0 = blockIdx.x * 64;
    const int k0 = s * 2048;
    uint32_t base = (smem_u32(dsm) + 1023u) & ~1023u;

    const uint8_t* Ae = g_adjf8 + (size_t)e*4096*4096;
    const uint8_t* Ze = g_Ztf8  + (size_t)e*128*4096;

    const int l7 = lane & 7;
    const int rA = wm*32 + l7 + ((lane >> 3) & 1)*8;
    const int klA = lane >> 4;
    const int rB = wn*32 + l7 + (lane >> 4)*8;
    const int klB = (lane >> 3) & 1;

    float acc[2][4][4] = {};

    issue_tile(base, 0, Ae, Ze, n0, k0,       tid);
    issue_tile(base, 1, Ae, Ze, n0, k0 + 128, tid);

    for (int kt = 0; kt < NKI; kt++) {
        if (kt + 1 < NKI) asm volatile("cp.async.wait_group 1;" ::: "memory");
        else              asm volatile("cp.async.wait_group 0;" ::: "memory");
        __syncthreads();
        if (kt + 2 < NKI)
            issue_tile(base, (kt + 2) % 3, Ae, Ze, n0, k0 + (kt+2)*128, tid);

        uint32_t sA = base + (uint32_t)(kt % 3) * STAGE_BYTES;
        uint32_t sB = sA + 8192;
#pragma unroll
        for (int s4 = 0; s4 < 4; s4++) {
            uint32_t a[2][4], b[2][4];
#pragma unroll
            for (int mi = 0; mi < 2; mi++) {
                int r = rA + mi*16;
                uint32_t ad = sA + (uint32_t)r*128
                            + (uint32_t)((((2*s4 + klA) ^ (r & 7))) << 4);
                ldm4(a[mi][0], a[mi][1], a[mi][2], a[mi][3], ad);
            }
#pragma unroll
            for (int p = 0; p < 2; p++) {
                int r = rB + p*16;
                uint32_t bd = sB + (uint32_t)r*128
                            + (uint32_t)((((2*s4 + klB) ^ (r & 7))) << 4);
                ldm4(b[p][0], b[p][1], b[p][2], b[p][3], bd);
            }
#pragma unroll
            for (int mi = 0; mi < 2; mi++)
#pragma unroll
                for (int nj = 0; nj < 4; nj++) {
                    int p = nj >> 1, hf = nj & 1;
                    mma16832f8(acc[mi][nj], a[mi], b[p][hf*2], b[p][hf*2 + 1]);
                }
        }
        __syncthreads();
    }

    const int g8 = lane >> 2, t2 = (lane & 3)*2;
#pragma unroll
    for (int mi = 0; mi < 2; mi++) {
#pragma unroll
        for (int nj = 0; nj < 4; nj++) {
            int c = wn*32 + nj*8 + t2;
            int b = c >> 6, h = c & 63;
            float* o = g_part + (size_t)(s*6 + e*2 + b)*NH;
            int row = n0 + wm*32 + mi*16 + g8;
            *(float2*)(o + (size_t)row*64 + h) =
                make_float2(acc[mi][nj][0], acc[mi][nj][1]);
            *(float2*)(o + (size_t)(row + 8)*64 + h) =
                make_float2(acc[mi][nj][2], acc[mi][nj][3]);
        }
    }
}

// ---------------- fused decode + next-step Z/pre (rewritten) -----------------
// 256 CTAs x 512 thr; CTA owns 16 nodes x 2 batches = 32 instances.
// 16 warps, 2 instances per warp, register-blocked decoder GEMV.
__global__ __launch_bounds__(512, 2) void k_decpre(const float* __restrict__ dw,
                                                   const float* __restrict__ db,
                                                   const float* __restrict__ ow,
                                                   const float* __restrict__ ob,
                                                   const float* __restrict__ cw,
                                                   const float* __restrict__ cb,
                                                   float* __restrict__ outp, int step) {
    extern __shared__ float F[];
    uint8_t* ZTB = (uint8_t*)F + ZTB_BYTE;
    const int tid = threadIdx.x;
    const int n0 = blockIdx.x * 16;

    // ---- preamble ----
    for (int q = tid; q < 8192; q += 512) {
        int j = q >> 6, h = q & 63;
        F[OFF_DW4 + (j >> 2)*256 + h*4 + (j & 3)] = dw[q];
    }
    for (int q = tid; q < 7680; q += 512) F[OFF_CWA + q] = g_cwAll[q];
    for (int q = tid; q < 1280; q += 512) F[OFF_CW + q] = cw[q];
    for (int q = tid; q < 640;  q += 512) {
        int inst = q / 20, k = q % 20;
        int b = inst >> 4, r = inst & 15;
        F[OFF_WIN + q] = g_window[(size_t)(b*4096 + n0 + r)*20 + k];
    }
    if (tid < 256) F[OFF_OW + tid] = ow[tid];
    else if (tid < 320) F[OFF_DB + tid - 256] = db[tid - 256];
    else if (tid < 384) F[OFF_CB + tid - 320] = cb[tid - 320];
    else if (tid < 388) F[OFF_OB + tid - 384] = ob[tid - 384];
    for (int q = tid; q < 384; q += 512) F[OFF_BALL + q] = g_bAll[q];
    __syncthreads();

    const int wid = tid >> 5, lane = tid & 31;
    const int i0 = wid*2, i1 = wid*2 + 1;
    const int b0 = i0 >> 4, r0 = i0 & 15;
    const int b1 = i1 >> 4, r1 = i1 & 15;
    const int c0 = lane, c1 = lane + 32;

    // ---- cond (K=20) for 2 instances x 2 cols ----
    float cv00 = F[OFF_CB + c0], cv01 = F[OFF_CB + c1];
    float cv10 = cv00, cv11 = cv01;
#pragma unroll
    for (int k = 0; k < 20; k++) {
        float w0 = F[OFF_WIN + i0*20 + k];
        float w1 = F[OFF_WIN + i1*20 + k];
        float a0 = F[OFF_CW + k*64 + c0];
        float a1 = F[OFF_CW + k*64 + c1];
        cv00 = fmaf(w0, a0, cv00); cv01 = fmaf(w0, a1, cv01);
        cv10 = fmaf(w1, a0, cv10); cv11 = fmaf(w1, a1, cv11);
    }

    // ---- encoded ----
    float ss00 = 0.f, ss01 = 0.f, ss10 = 0.f, ss11 = 0.f;
#pragma unroll
    for (int e = 0; e < 3; e++) {
        size_t o0 = (size_t)(e*2 + b0)*NH + (size_t)(n0 + r0)*64;
        size_t o1 = (size_t)(e*2 + b1)*NH + (size_t)(n0 + r1)*64;
        const float* pr0 = g_pre + (size_t)e*(8192*64) + (size_t)(b0*4096 + n0 + r0)*64;
        const float* pr1 = g_pre + (size_t)e*(8192*64) + (size_t)(b1*4096 + n0 + r1)*64;
        ss00 += tanhf((g_part[o0 + c0] + g_part[(size_t)6*NH + o0 + c0])*INV_ASCALE + pr0[c0]);
        ss01 += tanhf((g_part[o0 + c1] + g_part[(size_t)6*NH + o0 + c1])*INV_ASCALE + pr0[c1]);
        ss10 += tanhf((g_part[o1 + c0] + g_part[(size_t)6*NH + o1 + c0])*INV_ASCALE + pr1[c0]);
        ss11 += tanhf((g_part[o1 + c1] + g_part[(size_t)6*NH + o1 + c1])*INV_ASCALE + pr1[c1]);
    }
    float mk0 = g_mask[n0 + r0], mk1 = g_mask[n0 + r1];
    F[OFF_X + i0*128 + c0]        = cv00;
    F[OFF_X + i0*128 + c1]        = cv01;
    F[OFF_X + i0*128 + 64 + lane] = tanhf(ss00) * mk0;
    F[OFF_X + i0*128 + 96 + lane] = tanhf(ss01) * mk0;
    F[OFF_X + i1*128 + c0]        = cv10;
    F[OFF_X + i1*128 + c1]        = cv11;
    F[OFF_X + i1*128 + 64 + lane] = tanhf(ss10) * mk1;
    F[OFF_X + i1*128 + 96 + lane] = tanhf(ss11) * mk1;
    __syncwarp();

    // ---- decoder GEMV, register-blocked 2 instances ----
    float h00 = F[OFF_DB + c0], h01 = F[OFF_DB + c1];
    float h10 = h00, h11 = h01;
#pragma unroll
    for (int j4 = 0; j4 < 32; j4++) {
        float4 x0 = *(float4*)&F[OFF_X + i0*128 + j4*4];
        float4 x1 = *(float4*)&F[OFF_X + i1*128 + j4*4];
        float4 wa = *(float4*)&F[OFF_DW4 + j4*256 + c0*4];
        float4 wb = *(float4*)&F[OFF_DW4 + j4*256 + c1*4];
        h00 = fmaf(x0.x, wa.x, h00); h00 = fmaf(x0.y, wa.y, h00);
        h00 = fmaf(x0.z, wa.z, h00); h00 = fmaf(x0.w, wa.w, h00);
        h01 = fmaf(x0.x, wb.x, h01); h01 = fmaf(x0.y, wb.y, h01);
        h01 = fmaf(x0.z, wb.z, h01); h01 = fmaf(x0.w, wb.w, h01);
        h10 = fmaf(x1.x, wa.x, h10); h10 = fmaf(x1.y, wa.y, h10);
        h10 = fmaf(x1.z, wa.z, h10); h10 = fmaf(x1.w, wa.w, h10);
        h11 = fmaf(x1.x, wb.x, h11); h11 = fmaf(x1.y, wb.y, h11);
        h11 = fmaf(x1.z, wb.z, h11); h11 = fmaf(x1.w, wb.w, h11);
    }
    h00 = fmaxf(h00, 0.f); h01 = fmaxf(h01, 0.f);
    h10 = fmaxf(h10, 0.f); h11 = fmaxf(h11, 0.f);

    // ---- output projection: 8 partials (2 inst x 4 d), one shfl tree ----
    float od[8];
#pragma unroll
    for (int d = 0; d < 4; d++) {
        od[d]     = h00*F[OFF_OW + c0*4 + d] + h01*F[OFF_OW + c1*4 + d];
        od[4 + d] = h10*F[OFF_OW + c0*4 + d] + h11*F[OFF_OW + c1*4 + d];
    }
#pragma unroll
    for (int off = 16; off; off >>= 1)
#pragma unroll
        for (int d = 0; d < 8; d++)
            od[d] += __shfl_xor_sync(0xffffffffu, od[d], off);

    // ---- residual + window shift, instance i0 then i1 ----
#pragma unroll
    for (int ii = 0; ii < 2; ii++) {
        int inst = (ii == 0) ? i0 : i1;
        int bb   = (ii == 0) ? b0 : b1;
        int rr   = (ii == 0) ? r0 : r1;
        int obase = ii*4;
        float nvl = 0.f;
        if (lane < 4)
            nvl = F[OFF_WIN + inst*20 + 16 + lane]
                + tanhf(od[obase + lane] + F[OFF_OB + lane]);
        float old4 = (lane < 16) ? F[OFF_WIN + inst*20 + 4 + lane] : 0.f;
        float nvs  = __shfl_sync(0xffffffffu, nvl, lane & 3);
        float newv = (lane < 16) ? old4 : nvs;
        __syncwarp();
        if (lane < 20) {
            F[OFF_WIN + inst*20 + lane] = newv;
            g_window[(size_t)(bb*4096 + n0 + rr)*20 + lane] = newv;
        }
        if (lane < 4)
            outp[(((size_t)bb*PSTEPS + step)*4096 + (n0 + rr))*4 + lane] = nvl;
        __syncwarp();
    }
    __syncthreads();

    // ---- zpre: next-step Zt (fp8) + pre (fp32), all weights in smem ----
    if (tid < 384) {
        int mt = tid >> 6, h = tid & 63;
        float bias = F[OFF_BALL + tid];
        for (int inst = 0; inst < 32; inst++) {
            float a = bias;
#pragma unroll
            for (int k = 0; k < 20; k++)
                a = fmaf(F[OFF_WIN + inst*20 + k], F[OFF_CWA + (mt*20 + k)*64 + h], a);
            if (mt < 3) {
                int b = inst >> 4, r = inst & 15;
                __nv_fp8_e4m3 f8(a);
                ZTB[(mt*128 + b*64 + h)*16 + r] = *(uint8_t*)&f8;
            } else {
                F[OFF_PRE + inst*192 + (mt - 3)*64 + h] = a;
            }
        }
    }
    __syncthreads();

    // Zt writeback: 384 rows x 16B
    for (int q = tid; q < 384; q += 512)
        *(uint4*)(g_Ztf8 + (size_t)q*4096 + n0) = *(uint4*)(ZTB + q*16);
    // pre writeback: warp per instance pair, coalesced
#pragma unroll
    for (int ii = 0; ii < 2; ii++) {
        int inst = wid*2 + ii;
        int bb = inst >> 4, rr = inst & 15;
        size_t g = (size_t)(bb*4096 + n0 + rr);
        for (int q = lane; q < 192; q += 32)
            g_pre[(size_t)(q >> 6)*(8192*64) + g*64 + (q & 63)] = F[OFF_PRE + inst*192 + q];
    }
}

// ---------------------------------------------------------------------------
extern "C" void kernel_launch(void* const* d_in, const int* in_sizes, int n_in,
                              void* d_out, int out_size) {
    const float* ts   = (const float*)d_in[0];
    const float* adjs = (const float*)d_in[1];
    const float* cw   = (const float*)d_in[2];
    const float* cb   = (const float*)d_in[3];
    const float* w1   = (const float*)d_in[4];
    const float* w2   = (const float*)d_in[5];
    const float* encb = (const float*)d_in[6];
    const float* dw   = (const float*)d_in[7];
    const float* db   = (const float*)d_in[8];
    const float* ow   = (const float*)d_in[9];
    const float* ob   = (const float*)d_in[10];
    float* outp = (float*)d_out;

    cudaFuncSetAttribute(k_bigwmma, cudaFuncAttributeMaxDynamicSharedMemorySize, DSM_BYTES);
    cudaFuncSetAttribute(k_decpre,  cudaFuncAttributeMaxDynamicSharedMemorySize, DEC_SMEM_BYTES);

    k_init_window<<<640, 256>>>(ts);
    k_mask<<<16, 256>>>(adjs);
    k_convA<<<24576, 256>>>(adjs);
    k_prepw<<<dim3(6, 21), 64>>>(cw, cb, w1, w2, encb);
    k_zpre2<<<128, 256>>>();
    for (int p = 0; p < PSTEPS; p++) {
        k_bigwmma<<<dim3(64, 3, 2), 256, DSM_BYTES>>>();
        k_decpre<<<256, 512, DEC_SMEM_BYTES>>>(dw, db, ow, ob, cw, cb, outp, p);
    }
}

// round 14
// speedup vs baseline: 1.3014x; 1.0505x over previous
#include <cuda_runtime.h>
#include <cuda_bf16.h>
#include <cuda_fp8.h>
#include <cstdint>
#include <cstddef>

#define N_NODES 4096
#define PSTEPS 10
#define NH (N_NODES*64)          /* 262144 */
#define NKI 16                   /* K iterations per CTA: 2048 / 128 (fp8) */
#define STAGE_BYTES 24576        /* A 64x128B (8KB) + B 128x128B (16KB) */
#define DSM_BYTES (3*STAGE_BYTES + 1024)
#define ASCALE 4096.0f
#define INV_ASCALE (1.0f/4096.0f)

/* decpre smem float offsets */
#define OFF_DW4  0               /* [32][64][4] = 8192 f, conflict-free GEMV layout */
#define OFF_CW   8192            /* 1280 f */
#define OFF_OW   9472            /* 256 f */
#define OFF_DB   9728            /* 64 f */
#define OFF_CB   9792            /* 64 f */
#define OFF_OB   9856            /* 8 f (4 + pad) */
#define OFF_WIN  9864            /* 16*20 = 320 f */
#define OFF_X    10184           /* 16*128 = 2048 f */
#define OFF_PRE  12232           /* 16*192 = 3072 f -> ends 15304 */
#define ZTB_BYTE 61216           /* 15304*4, 16B aligned; 192*16 = 3072 B */
#define DEC_SMEM_BYTES (ZTB_BYTE + 3072)

/* k_setup block partitions */
#define SB_CONVA 24576
#define SB_INIT  (SB_CONVA + 640)
#define SB_MASK  (SB_INIT + 16)
#define SB_PREPW (SB_MASK + 32)

// ---------------- device scratch -------------------------------------------
__device__ float g_window[2*N_NODES*20];           // [B][N][T*D]
__device__ float g_pre[3*2*N_NODES*64];            // [E][B*N][H]
__device__ float g_part[12*NH];                    // [S=2][E=3][B=2][N][H]
__device__ float g_mask[N_NODES];
__device__ float g_cwAll[6*20*64];                 // combined conv@W weights
__device__ float g_bAll[6*64];                     // combined biases
__device__ uint8_t g_Ztf8[3UL*128*4096];           // [E][b*64+h][m] fp8 e4m3
__device__ uint8_t g_adjf8[3UL*4096*4096];         // fp8 e4m3 adjacency * 4096

// ---------------- helpers ---------------------------------------------------
__device__ __forceinline__ uint32_t smem_u32(const void* p) {
    uint32_t a;
    asm("{ .reg .u64 t; cvta.to.shared.u64 t, %1; cvt.u32.u64 %0, t; }" : "=r"(a) : "l"(p));
    return a;
}
__device__ __forceinline__ void ldm4(uint32_t& r0, uint32_t& r1, uint32_t& r2,
                                     uint32_t& r3, uint32_t a) {
    asm volatile("ldmatrix.sync.aligned.m8n8.x4.shared.b16 {%0,%1,%2,%3}, [%4];"
                 : "=r"(r0), "=r"(r1), "=r"(r2), "=r"(r3) : "r"(a));
}
__device__ __forceinline__ void mma16832f8(float* c, const uint32_t* a,
                                           uint32_t b0, uint32_t b1) {
    asm volatile(
        "mma.sync.aligned.m16n8k32.row.col.f32.e4m3.e4m3.f32 "
        "{%0,%1,%2,%3}, {%4,%5,%6,%7}, {%8,%9}, {%0,%1,%2,%3};"
        : "+f"(c[0]), "+f"(c[1]), "+f"(c[2]), "+f"(c[3])
        : "r"(a[0]), "r"(a[1]), "r"(a[2]), "r"(a[3]), "r"(b0), "r"(b1));
}

// ---------------- merged one-time setup -------------------------------------
// blocks [0, 24576): convA | [24576, 25216): init | [25216, 25232): mask
// [25232, 25264): prepw (flattened 6*21*64 = 8064)
__global__ __launch_bounds__(256) void k_setup(const float* __restrict__ ts,
                                               const float* __restrict__ adjs,
                                               const float* __restrict__ cw,
                                               const float* __restrict__ cb,
                                               const float* __restrict__ w1,
                                               const float* __restrict__ w2,
                                               const float* __restrict__ encb) {
    int bid = blockIdx.x, tid = threadIdx.x;
    if (bid < SB_CONVA) {
        size_t i = ((size_t)bid * 256 + tid) * 8;
        float4 a = *(const float4*)(adjs + i);
        float4 b = *(const float4*)(adjs + i + 4);
        __nv_fp8x4_e4m3 lo(make_float4(a.x*ASCALE, a.y*ASCALE, a.z*ASCALE, a.w*ASCALE));
        __nv_fp8x4_e4m3 hi(make_float4(b.x*ASCALE, b.y*ASCALE, b.z*ASCALE, b.w*ASCALE));
        uint2 v; v.x = lo.__x; v.y = hi.__x;
        *(uint2*)(g_adjf8 + i) = v;
    } else if (bid < SB_INIT) {
        int idx = (bid - SB_CONVA) * 256 + tid;
        int d = idx & 3;
        int r = idx >> 2;
        int t = r % 5;
        int bn = r / 5;
        int n = bn & (N_NODES - 1);
        int b = bn >> 12;
        g_window[idx] = ts[(((size_t)(b*5 + t))*N_NODES + n)*4 + d];
    } else if (bid < SB_MASK) {
        int m = (bid - SB_INIT) * 256 + tid;
        float v = 0.f;
        for (size_t i = m; i < (size_t)3*N_NODES*N_NODES; i += N_NODES) {
            if (adjs[i] > 0.f) { v = 1.f; break; }
        }
        g_mask[m] = v;
    } else {
        int idx = (bid - SB_MASK) * 256 + tid;      // [0, 8192)
        if (idx < 8064) {
            int mt = idx / (21*64);
            int rem = idx % (21*64);
            int row = rem >> 6, h = rem & 63;
            int e = (mt < 3) ? mt : mt - 3;
            const float* W = ((mt < 3) ? w1 : w2) + e*64*64;
            const float* src = (row < 20) ? (cw + row*64) : cb;
            float a = 0.f;
#pragma unroll 8
            for (int f = 0; f < 64; f++) a = fmaf(src[f], W[f*64 + h], a);
            if (row < 20) {
                g_cwAll[(mt*20 + row)*64 + h] = a;
            } else {
                if (mt >= 3) a += encb[e*64 + h];
                g_bAll[mt*64 + h] = a;
            }
        }
    }
}

// ---------------- initial Zt/pre (before step 0) ----------------------------
__global__ __launch_bounds__(256) void k_zpre2() {
    __shared__ float sW[6*20*64];
    __shared__ float sB[6*64];
    __shared__ float sWin[64][21];
    int tid = threadIdx.x;
    int g0 = blockIdx.x * 64;

    for (int q = tid; q < 6*20*64; q += 256) sW[q] = g_cwAll[q];
    for (int q = tid; q < 6*64;    q += 256) sB[q] = g_bAll[q];
    for (int q = tid; q < 64*20;   q += 256)
        sWin[q/20][q%20] = g_window[(size_t)(g0 + q/20)*20 + q%20];
    __syncthreads();

    int tx = tid & 15, ty = tid >> 4;
    int h0 = tx * 4;
    int b  = g0 >> 12;
    int m0 = (g0 & 4095) + ty*4;

#pragma unroll
    for (int mt = 0; mt < 6; mt++) {
        float acc[4][4];
#pragma unroll
        for (int i = 0; i < 4; i++)
#pragma unroll
            for (int j = 0; j < 4; j++) acc[i][j] = sB[mt*64 + h0 + j];
#pragma unroll
        for (int k = 0; k < 20; k++) {
            float4 w = *(float4*)&sW[(mt*20 + k)*64 + h0];
            float wv[4] = {w.x, w.y, w.z, w.w};
#pragma unroll
            for (int i = 0; i < 4; i++) {
                float a = sWin[ty*4 + i][k];
#pragma unroll
                for (int j = 0; j < 4; j++) acc[i][j] = fmaf(a, wv[j], acc[i][j]);
            }
        }
        if (mt < 3) {
#pragma unroll
            for (int j = 0; j < 4; j++) {
                __nv_fp8x4_e4m3 p4(make_float4(acc[0][j], acc[1][j], acc[2][j], acc[3][j]));
                *(uint32_t*)(g_Ztf8 + (size_t)(mt*128 + b*64 + h0 + j)*4096 + m0) = p4.__x;
            }
        } else {
            int e = mt - 3;
#pragma unroll
            for (int i = 0; i < 4; i++)
                *(float4*)(g_pre + (size_t)e*(8192*64) + (size_t)(g0 + ty*4 + i)*64 + h0) =
                    make_float4(acc[i][0], acc[i][1], acc[i][2], acc[i][3]);
        }
    }
}

// ---------------- big GEMM on fp8 mma.sync (unchanged) -----------------------
__device__ __forceinline__ void issue_tile(uint32_t base, int st,
                                           const uint8_t* Ae,
                                           const uint8_t* Ze,
                                           int n0, int kk, int tid) {
    uint32_t sA = base + (uint32_t)st * STAGE_BYTES;
    uint32_t sB = sA + 8192;
#pragma unroll
    for (int k = 0; k < 2; k++) {
        int q = tid + k*256;
        int r = q >> 3, c = q & 7;
        uint32_t off = (uint32_t)r*128 + (uint32_t)((c ^ (r & 7)) << 4);
        const void* g = Ae + (size_t)(n0 + r)*4096 + kk + c*16;
        asm volatile("cp.async.cg.shared.global [%0], [%1], 16;" :: "r"(sA + off), "l"(g));
    }
#pragma unroll
    for (int k = 0; k < 4; k++) {
        int q = tid + k*256;
        int r = q >> 3, c = q & 7;
        uint32_t off = (uint32_t)r*128 + (uint32_t)((c ^ (r & 7)) << 4);
        const void* g = Ze + (size_t)r*4096 + kk + c*16;
        asm volatile("cp.async.cg.shared.global [%0], [%1], 16;" :: "r"(sB + off), "l"(g));
    }
    asm volatile("cp.async.commit_group;" ::: "memory");
}

__global__ __launch_bounds__(256, 2) void k_bigwmma() {
    extern __shared__ __align__(1024) char dsm[];
    const int tid = threadIdx.x;
    const int lane = tid & 31, wid = tid >> 5;
    const int wm = wid & 1, wn = wid >> 1;
    const int e = blockIdx.y, s = blockIdx.z;
    const int n0 = blockIdx.x * 64;
    const int k0 = s * 2048;
    uint32_t base = (smem_u32(dsm) + 1023u) & ~1023u;

    const uint8_t* Ae = g_adjf8 + (size_t)e*4096*4096;
    const uint8_t* Ze = g_Ztf8  + (size_t)e*128*4096;

    const int l7 = lane & 7;
    const int rA = wm*32 + l7 + ((lane >> 3) & 1)*8;
    const int klA = lane >> 4;
    const int rB = wn*32 + l7 + (lane >> 4)*8;
    const int klB = (lane >> 3) & 1;

    float acc[2][4][4] = {};

    issue_tile(base, 0, Ae, Ze, n0, k0,       tid);
    issue_tile(base, 1, Ae, Ze, n0, k0 + 128, tid);

    for (int kt = 0; kt < NKI; kt++) {
        if (kt + 1 < NKI) asm volatile("cp.async.wait_group 1;" ::: "memory");
        else              asm volatile("cp.async.wait_group 0;" ::: "memory");
        __syncthreads();
        if (kt + 2 < NKI)
            issue_tile(base, (kt + 2) % 3, Ae, Ze, n0, k0 + (kt+2)*128, tid);

        uint32_t sA = base + (uint32_t)(kt % 3) * STAGE_BYTES;
        uint32_t sB = sA + 8192;
#pragma unroll
        for (int s4 = 0; s4 < 4; s4++) {
            uint32_t a[2][4], b[2][4];
#pragma unroll
            for (int mi = 0; mi < 2; mi++) {
                int r = rA + mi*16;
                uint32_t ad = sA + (uint32_t)r*128
                            + (uint32_t)((((2*s4 + klA) ^ (r & 7))) << 4);
                ldm4(a[mi][0], a[mi][1], a[mi][2], a[mi][3], ad);
            }
#pragma unroll
            for (int p = 0; p < 2; p++) {
                int r = rB + p*16;
                uint32_t bd = sB + (uint32_t)r*128
                            + (uint32_t)((((2*s4 + klB) ^ (r & 7))) << 4);
                ldm4(b[p][0], b[p][1], b[p][2], b[p][3], bd);
            }
#pragma unroll
            for (int mi = 0; mi < 2; mi++)
#pragma unroll
                for (int nj = 0; nj < 4; nj++) {
                    int p = nj >> 1, hf = nj & 1;
                    mma16832f8(acc[mi][nj], a[mi], b[p][hf*2], b[p][hf*2 + 1]);
                }
        }
        __syncthreads();
    }

    const int g8 = lane >> 2, t2 = (lane & 3)*2;
#pragma unroll
    for (int mi = 0; mi < 2; mi++) {
#pragma unroll
        for (int nj = 0; nj < 4; nj++) {
            int c = wn*32 + nj*8 + t2;
            int b = c >> 6, h = c & 63;
            float* o = g_part + (size_t)(s*6 + e*2 + b)*NH;
            int row = n0 + wm*32 + mi*16 + g8;
            *(float2*)(o + (size_t)row*64 + h) =
                make_float2(acc[mi][nj][0], acc[mi][nj][1]);
            *(float2*)(o + (size_t)(row + 8)*64 + h) =
                make_float2(acc[mi][nj][2], acc[mi][nj][3]);
        }
    }
}

// ---------------- fused decode + next-step Z/pre (R11 + conflict-free dw) ----
// 512 CTAs x 512 thr = 16 warps = 16 instances (same b per CTA).
__global__ __launch_bounds__(512, 2) void k_decpre(const float* __restrict__ dw,
                                                   const float* __restrict__ db,
                                                   const float* __restrict__ ow,
                                                   const float* __restrict__ ob,
                                                   const float* __restrict__ cw,
                                                   const float* __restrict__ cb,
                                                   float* __restrict__ outp, int step) {
    extern __shared__ float F[];
    uint8_t* ztb = (uint8_t*)F + ZTB_BYTE;
    const int tid = threadIdx.x;
    const int g0 = blockIdx.x * 16;

    // preamble: dec_w in [j4][h][4] layout -> GEMV float4 loads conflict-free
    for (int q = tid; q < 8192; q += 512) {
        int j = q >> 6, h = q & 63;
        F[OFF_DW4 + (j >> 2)*256 + h*4 + (j & 3)] = dw[q];
    }
    for (int q = tid; q < 1280; q += 512) F[OFF_CW + q] = cw[q];
    if (tid < 256) F[OFF_OW + tid] = ow[tid];
    else if (tid < 320) F[OFF_DB + tid - 256] = db[tid - 256];
    else if (tid < 384) F[OFF_CB + tid - 320] = cb[tid - 320];
    else if (tid < 388) F[OFF_OB + tid - 384] = ob[tid - 384];
    for (int q = tid; q < 320; q += 512)
        F[OFF_WIN + q] = g_window[(size_t)(g0 + q/20)*20 + q%20];
    __syncthreads();

    const int w = tid >> 5, lane = tid & 31;
    const int g = g0 + w, b = g >> 12, n = g & 4095;
    const int c0 = lane, c1 = lane + 32;

    // ---- decode (warp-local) ----
    float cv0 = F[OFF_CB + c0], cv1 = F[OFF_CB + c1];
#pragma unroll
    for (int k = 0; k < 20; k++) {
        float wk = F[OFF_WIN + w*20 + k];
        cv0 = fmaf(wk, F[OFF_CW + k*64 + c0], cv0);
        cv1 = fmaf(wk, F[OFF_CW + k*64 + c1], cv1);
    }
    float ss0 = 0.f, ss1 = 0.f;
#pragma unroll
    for (int e = 0; e < 3; e++) {
        size_t o0 = (size_t)(e*2 + b)*NH + (size_t)n*64;
        const float* pr = g_pre + (size_t)e*(8192*64) + (size_t)g*64;
        float p0 = (g_part[o0 + c0] + g_part[(size_t)6*NH + o0 + c0]) * INV_ASCALE + pr[c0];
        float p1 = (g_part[o0 + c1] + g_part[(size_t)6*NH + o0 + c1]) * INV_ASCALE + pr[c1];
        ss0 += tanhf(p0); ss1 += tanhf(p1);
    }
    float mk = g_mask[n];
    F[OFF_X + w*128 + c0]      = cv0;
    F[OFF_X + w*128 + c1]      = cv1;
    F[OFF_X + w*128 + 64 + c0] = tanhf(ss0) * mk;
    F[OFF_X + w*128 + 96 + c0] = tanhf(ss1) * mk;
    __syncwarp();

    float h0 = F[OFF_DB + c0], h1 = F[OFF_DB + c1];
#pragma unroll
    for (int j4 = 0; j4 < 32; j4++) {
        float4 xx = *(float4*)&F[OFF_X + w*128 + j4*4];
        float4 wa = *(float4*)&F[OFF_DW4 + j4*256 + c0*4];
        float4 wb = *(float4*)&F[OFF_DW4 + j4*256 + c1*4];
        h0 = fmaf(xx.x, wa.x, h0); h0 = fmaf(xx.y, wa.y, h0);
        h0 = fmaf(xx.z, wa.z, h0); h0 = fmaf(xx.w, wa.w, h0);
        h1 = fmaf(xx.x, wb.x, h1); h1 = fmaf(xx.y, wb.y, h1);
        h1 = fmaf(xx.z, wb.z, h1); h1 = fmaf(xx.w, wb.w, h1);
    }
    h0 = fmaxf(h0, 0.f); h1 = fmaxf(h1, 0.f);

    float od[4];
#pragma unroll
    for (int d = 0; d < 4; d++)
        od[d] = h0*F[OFF_OW + c0*4 + d] + h1*F[OFF_OW + c1*4 + d];
#pragma unroll
    for (int off = 16; off; off >>= 1)
#pragma unroll
        for (int d = 0; d < 4; d++)
            od[d] += __shfl_xor_sync(0xffffffffu, od[d], off);

    float nvl = 0.f;
    if (lane < 4) nvl = F[OFF_WIN + w*20 + 16 + lane] + tanhf(od[lane] + F[OFF_OB + lane]);
    float old4 = (lane < 16) ? F[OFF_WIN + w*20 + 4 + lane] : 0.f;
    float nvs  = __shfl_sync(0xffffffffu, nvl, lane & 3);
    float newv = (lane < 16) ? old4 : nvs;
    __syncwarp();
    if (lane < 20) {
        F[OFF_WIN + w*20 + lane] = newv;
        g_window[(size_t)g*20 + lane] = newv;
    }
    if (lane < 4)
        outp[(((size_t)b*PSTEPS + step)*4096 + n)*4 + lane] = nvl;
    __syncthreads();

    // ---- zpre: next-step Zt (fp8 staged) + pre (fp32 staged) ----
    if (tid < 384) {
        int mt = tid >> 6, h = tid & 63;
        float bias = g_bAll[tid];
        for (int i = 0; i < 16; i++) {
            float a = bias;
#pragma unroll
            for (int k = 0; k < 20; k++)
                a = fmaf(F[OFF_WIN + i*20 + k], g_cwAll[(mt*20 + k)*64 + h], a);
            if (mt < 3) {
                __nv_fp8_e4m3 f8(a);
                ztb[(mt*64 + h)*16 + i] = *(uint8_t*)&f8;
            } else {
                F[OFF_PRE + i*192 + (mt - 3)*64 + h] = a;
            }
        }
    }
    __syncthreads();

    // Zt writeback: 192 rows x 16B (block is single-b, 16 consecutive n)
    const int bb = g0 >> 12, n0v = g0 & 4095;
    for (int q = tid; q < 192; q += 512) {
        int mt = q >> 6, h = q & 63;
        *(uint4*)(g_Ztf8 + (size_t)(mt*128 + bb*64 + h)*4096 + n0v) =
            *(uint4*)(ztb + q*16);
    }
    // pre writeback: warp per instance, coalesced
    for (int q = lane; q < 192; q += 32)
        g_pre[(size_t)(q >> 6)*(8192*64) + (size_t)g*64 + (q & 63)] =
            F[OFF_PRE + w*192 + q];
}

// ---------------------------------------------------------------------------
extern "C" void kernel_launch(void* const* d_in, const int* in_sizes, int n_in,
                              void* d_out, int out_size) {
    const float* ts   = (const float*)d_in[0];
    const float* adjs = (const float*)d_in[1];
    const float* cw   = (const float*)d_in[2];
    const float* cb   = (const float*)d_in[3];
    const float* w1   = (const float*)d_in[4];
    const float* w2   = (const float*)d_in[5];
    const float* encb = (const float*)d_in[6];
    const float* dw   = (const float*)d_in[7];
    const float* db   = (const float*)d_in[8];
    const float* ow   = (const float*)d_in[9];
    const float* ob   = (const float*)d_in[10];
    float* outp = (float*)d_out;

    cudaFuncSetAttribute(k_bigwmma, cudaFuncAttributeMaxDynamicSharedMemorySize, DSM_BYTES);
    cudaFuncSetAttribute(k_decpre,  cudaFuncAttributeMaxDynamicSharedMemorySize, DEC_SMEM_BYTES);

    // Launch order chosen so the 4th launch (ncu's capture point) = k_decpre.
    k_setup<<<SB_PREPW, 256>>>(ts, adjs, cw, cb, w1, w2, encb);   // 1
    k_zpre2<<<128, 256>>>();                                      // 2
    for (int p = 0; p < PSTEPS; p++) {
        k_bigwmma<<<dim3(64, 3, 2), 256, DSM_BYTES>>>();          // 3, 5, 7, ...
        k_decpre<<<512, 512, DEC_SMEM_BYTES>>>(dw, db, ow, ob, cw, cb, outp, p); // 4 <- profiled
    }
}

// round 17
// speedup vs baseline: 1.3915x; 1.0693x over previous
#include <cuda_runtime.h>
#include <cuda_bf16.h>
#include <cuda_fp8.h>
#include <cstdint>
#include <cstddef>

#define N_NODES 4096
#define PSTEPS 10
#define NH (N_NODES*64)          /* 262144 */
#define STG2 32768               /* A 128x128B (16KB) + B 128x128B (16KB) */
#define DSM_BYTES (3*STG2 + 1024)
#define ASCALE 4096.0f
#define INV_ASCALE (1.0f/4096.0f)

/* decpre smem float offsets */
#define OFF_DW4  0               /* [32][64][4] = 8192 f, conflict-free GEMV layout */
#define OFF_CW   8192            /* 1280 f */
#define OFF_OW   9472            /* 256 f */
#define OFF_DB   9728            /* 64 f */
#define OFF_CB   9792            /* 64 f */
#define OFF_OB   9856            /* 8 f (4 + pad) */
#define OFF_WIN  9864            /* 16*20 = 320 f */
#define OFF_X    10184           /* 16*128 = 2048 f */
#define OFF_PRE  12232           /* 16*192 = 3072 f -> ends 15304 */
#define ZTB_BYTE 61216           /* 15304*4, 16B aligned; 192*16 = 3072 B */
#define DEC_SMEM_BYTES (ZTB_BYTE + 3072)

// ---------------- device scratch -------------------------------------------
__device__ float g_window[2*N_NODES*20];           // [B][N][T*D]
__device__ float g_pre[3*2*N_NODES*64];            // [E][B*N][H]
__device__ float g_part[18*NH];                    // [S=3][E=3][B=2][N][H]
__device__ float g_mask[N_NODES];
__device__ float g_cwAll[6*20*64];                 // combined conv@W weights
__device__ float g_bAll[6*64];                     // combined biases
__device__ uint8_t g_Ztf8[3UL*128*4096];           // [E][b*64+h][m] fp8 e4m3
__device__ uint8_t g_adjf8[3UL*4096*4096];         // fp8 e4m3 adjacency * 4096

// ---------------- helpers ---------------------------------------------------
__device__ __forceinline__ uint32_t smem_u32(const void* p) {
    uint32_t a;
    asm("{ .reg .u64 t; cvta.to.shared.u64 t, %1; cvt.u32.u64 %0, t; }" : "=r"(a) : "l"(p));
    return a;
}
__device__ __forceinline__ void ldm4(uint32_t& r0, uint32_t& r1, uint32_t& r2,
                                     uint32_t& r3, uint32_t a) {
    asm volatile("ldmatrix.sync.aligned.m8n8.x4.shared.b16 {%0,%1,%2,%3}, [%4];"
                 : "=r"(r0), "=r"(r1), "=r"(r2), "=r"(r3) : "r"(a));
}
__device__ __forceinline__ void mma16832f8(float* c, const uint32_t* a,
                                           uint32_t b0, uint32_t b1) {
    asm volatile(
        "mma.sync.aligned.m16n8k32.row.col.f32.e4m3.e4m3.f32 "
        "{%0,%1,%2,%3}, {%4,%5,%6,%7}, {%8,%9}, {%0,%1,%2,%3};"
        : "+f"(c[0]), "+f"(c[1]), "+f"(c[2]), "+f"(c[3])
        : "r"(a[0]), "r"(a[1]), "r"(a[2]), "r"(a[3]), "r"(b0), "r"(b1));
}

// ---------------- one-time setup (split for profiler steering) ---------------
// setup_a: adjacency fp32 -> fp8*4096 (24576 blocks)
__global__ __launch_bounds__(256) void k_setup_a(const float* __restrict__ adjs) {
    size_t i = ((size_t)blockIdx.x * 256 + threadIdx.x) * 8;
    float4 a = *(const float4*)(adjs + i);
    float4 b = *(const float4*)(adjs + i + 4);
    __nv_fp8x4_e4m3 lo(make_float4(a.x*ASCALE, a.y*ASCALE, a.z*ASCALE, a.w*ASCALE));
    __nv_fp8x4_e4m3 hi(make_float4(b.x*ASCALE, b.y*ASCALE, b.z*ASCALE, b.w*ASCALE));
    uint2 v; v.x = lo.__x; v.y = hi.__x;
    *(uint2*)(g_adjf8 + i) = v;
}

// setup_b: window init (640) | mask (16) | prepw (32)
__global__ __launch_bounds__(256) void k_setup_b(const float* __restrict__ ts,
                                                 const float* __restrict__ adjs,
                                                 const float* __restrict__ cw,
                                                 const float* __restrict__ cb,
                                                 const float* __restrict__ w1,
                                                 const float* __restrict__ w2,
                                                 const float* __restrict__ encb) {
    int bid = blockIdx.x, tid = threadIdx.x;
    if (bid < 640) {
        int idx = bid * 256 + tid;
        int d = idx & 3;
        int r = idx >> 2;
        int t = r % 5;
        int bn = r / 5;
        int n = bn & (N_NODES - 1);
        int b = bn >> 12;
        g_window[idx] = ts[(((size_t)(b*5 + t))*N_NODES + n)*4 + d];
    } else if (bid < 656) {
        int m = (bid - 640) * 256 + tid;
        float v = 0.f;
        for (size_t i = m; i < (size_t)3*N_NODES*N_NODES; i += N_NODES) {
            if (adjs[i] > 0.f) { v = 1.f; break; }
        }
        g_mask[m] = v;
    } else {
        int idx = (bid - 656) * 256 + tid;          // [0, 8192)
        if (idx < 8064) {
            int mt = idx / (21*64);
            int rem = idx % (21*64);
            int row = rem >> 6, h = rem & 63;
            int e = (mt < 3) ? mt : mt - 3;
            const float* W = ((mt < 3) ? w1 : w2) + e*64*64;
            const float* src = (row < 20) ? (cw + row*64) : cb;
            float a = 0.f;
#pragma unroll 8
            for (int f = 0; f < 64; f++) a = fmaf(src[f], W[f*64 + h], a);
            if (row < 20) {
                g_cwAll[(mt*20 + row)*64 + h] = a;
            } else {
                if (mt >= 3) a += encb[e*64 + h];
                g_bAll[mt*64 + h] = a;
            }
        }
    }
}

// ---------------- initial Zt/pre (before step 0) ----------------------------
__global__ __launch_bounds__(256) void k_zpre2() {
    __shared__ float sW[6*20*64];
    __shared__ float sB[6*64];
    __shared__ float sWin[64][21];
    int tid = threadIdx.x;
    int g0 = blockIdx.x * 64;

    for (int q = tid; q < 6*20*64; q += 256) sW[q] = g_cwAll[q];
    for (int q = tid; q < 6*64;    q += 256) sB[q] = g_bAll[q];
    for (int q = tid; q < 64*20;   q += 256)
        sWin[q/20][q%20] = g_window[(size_t)(g0 + q/20)*20 + q%20];
    __syncthreads();

    int tx = tid & 15, ty = tid >> 4;
    int h0 = tx * 4;
    int b  = g0 >> 12;
    int m0 = (g0 & 4095) + ty*4;

#pragma unroll
    for (int mt = 0; mt < 6; mt++) {
        float acc[4][4];
#pragma unroll
        for (int i = 0; i < 4; i++)
#pragma unroll
            for (int j = 0; j < 4; j++) acc[i][j] = sB[mt*64 + h0 + j];
#pragma unroll
        for (int k = 0; k < 20; k++) {
            float4 w = *(float4*)&sW[(mt*20 + k)*64 + h0];
            float wv[4] = {w.x, w.y, w.z, w.w};
#pragma unroll
            for (int i = 0; i < 4; i++) {
                float a = sWin[ty*4 + i][k];
#pragma unroll
                for (int j = 0; j < 4; j++) acc[i][j] = fmaf(a, wv[j], acc[i][j]);
            }
        }
        if (mt < 3) {
#pragma unroll
            for (int j = 0; j < 4; j++) {
                __nv_fp8x4_e4m3 p4(make_float4(acc[0][j], acc[1][j], acc[2][j], acc[3][j]));
                *(uint32_t*)(g_Ztf8 + (size_t)(mt*128 + b*64 + h0 + j)*4096 + m0) = p4.__x;
            }
        } else {
            int e = mt - 3;
#pragma unroll
            for (int i = 0; i < 4; i++)
                *(float4*)(g_pre + (size_t)e*(8192*64) + (size_t)(g0 + ty*4 + i)*64 + h0) =
                    make_float4(acc[i][0], acc[i][1], acc[i][2], acc[i][3]);
        }
    }
}

// ---------------- big GEMM: M=128 tile, 3-way uneven K-split -----------------
// grid (32 row-tiles, E=3, S=3) = 288 CTAs = one full wave at 2/SM.
// 256 thr, 8 warps (2m x 4n), warp tile 64x32, KC=128B, splits 11/11/10 iters.
__device__ __forceinline__ void issue2(uint32_t base, int st,
                                       const uint8_t* Ae, const uint8_t* Ze,
                                       int n0, int kk, int tid) {
    uint32_t sA = base + (uint32_t)st * STG2;
    uint32_t sB = sA + 16384;
#pragma unroll
    for (int k = 0; k < 4; k++) {                  // A: 128 rows x 8 x 16B
        int q = tid + k*256;
        int r = q >> 3, c = q & 7;
        uint32_t off = (uint32_t)r*128 + (uint32_t)((c ^ (r & 7)) << 4);
        const void* g = Ae + (size_t)(n0 + r)*4096 + kk + c*16;
        asm volatile("cp.async.cg.shared.global [%0], [%1], 16;" :: "r"(sA + off), "l"(g));
    }
#pragma unroll
    for (int k = 0; k < 4; k++) {                  // B: 128 rows x 8 x 16B
        int q = tid + k*256;
        int r = q >> 3, c = q & 7;
        uint32_t off = (uint32_t)r*128 + (uint32_t)((c ^ (r & 7)) << 4);
        const void* g = Ze + (size_t)r*4096 + kk + c*16;
        asm volatile("cp.async.cg.shared.global [%0], [%1], 16;" :: "r"(sB + off), "l"(g));
    }
    asm volatile("cp.async.commit_group;" ::: "memory");
}

__global__ __launch_bounds__(256, 2) void k_bigwmma() {
    extern __shared__ __align__(1024) char dsm[];
    const int tid = threadIdx.x;
    const int lane = tid & 31, wid = tid >> 5;
    const int wm = wid & 1, wn = wid >> 1;         // warp 64(m) x 32(n)
    const int e = blockIdx.y, s = blockIdx.z;
    const int n0 = blockIdx.x * 128;
    const int k0 = s * 1408;                       // 0 / 1408 / 2816
    const int nkt = (s == 2) ? 10 : 11;
    uint32_t base = (smem_u32(dsm) + 1023u) & ~1023u;

    const uint8_t* Ae = g_adjf8 + (size_t)e*4096*4096;
    const uint8_t* Ze = g_Ztf8  + (size_t)e*128*4096;

    const int l7 = lane & 7;
    const int rAb = wm*64 + l7 + ((lane >> 3) & 1)*8;   // + mi*16
    const int klA = lane >> 4;
    const int rBb = wn*32 + l7 + (lane >> 4)*8;          // + p*16
    const int klB = (lane >> 3) & 1;

    float acc[4][4][4] = {};

    issue2(base, 0, Ae, Ze, n0, k0,       tid);
    issue2(base, 1, Ae, Ze, n0, k0 + 128, tid);

    for (int kt = 0; kt < nkt; kt++) {
        if (kt + 1 < nkt) asm volatile("cp.async.wait_group 1;" ::: "memory");
        else              asm volatile("cp.async.wait_group 0;" ::: "memory");
        __syncthreads();
        if (kt + 2 < nkt)
            issue2(base, (kt + 2) % 3, Ae, Ze, n0, k0 + (kt+2)*128, tid);

        uint32_t sA = base + (uint32_t)(kt % 3) * STG2;
        uint32_t sB = sA + 16384;
#pragma unroll
        for (int s4 = 0; s4 < 4; s4++) {           // 32 k-bytes each
            uint32_t a[4][4], b[2][4];
#pragma unroll
            for (int mi = 0; mi < 4; mi++) {
                int r = rAb + mi*16;
                uint32_t ad = sA + (uint32_t)r*128
                            + (uint32_t)((((2*s4 + klA) ^ (r & 7))) << 4);
                ldm4(a[mi][0], a[mi][1], a[mi][2], a[mi][3], ad);
            }
#pragma unroll
            for (int p = 0; p < 2; p++) {
                int r = rBb + p*16;
                uint32_t bd = sB + (uint32_t)r*128
                            + (uint32_t)((((2*s4 + klB) ^ (r & 7))) << 4);
                ldm4(b[p][0], b[p][1], b[p][2], b[p][3], bd);
            }
#pragma unroll
            for (int mi = 0; mi < 4; mi++)
#pragma unroll
                for (int nj = 0; nj < 4; nj++) {
                    int p = nj >> 1, hf = nj & 1;
                    mma16832f8(acc[mi][nj], a[mi], b[p][hf*2], b[p][hf*2 + 1]);
                }
        }
        __syncthreads();
    }

    const int g8 = lane >> 2, t2 = (lane & 3)*2;
#pragma unroll
    for (int mi = 0; mi < 4; mi++) {
#pragma unroll
        for (int nj = 0; nj < 4; nj++) {
            int c = wn*32 + nj*8 + t2;
            int b = c >> 6, h = c & 63;
            float* o = g_part + (size_t)(s*6 + e*2 + b)*NH;
            int row = n0 + wm*64 + mi*16 + g8;
            *(float2*)(o + (size_t)row*64 + h) =
                make_float2(acc[mi][nj][0], acc[mi][nj][1]);
            *(float2*)(o + (size_t)(row + 8)*64 + h) =
                make_float2(acc[mi][nj][2], acc[mi][nj][3]);
        }
    }
}

// ---------------- fused decode + next-step Z/pre (3-split sum) ---------------
__global__ __launch_bounds__(512, 2) void k_decpre(const float* __restrict__ dw,
                                                   const float* __restrict__ db,
                                                   const float* __restrict__ ow,
                                                   const float* __restrict__ ob,
                                                   const float* __restrict__ cw,
                                                   const float* __restrict__ cb,
                                                   float* __restrict__ outp, int step) {
    extern __shared__ float F[];
    uint8_t* ztb = (uint8_t*)F + ZTB_BYTE;
    const int tid = threadIdx.x;
    const int g0 = blockIdx.x * 16;

    for (int q = tid; q < 8192; q += 512) {
        int j = q >> 6, h = q & 63;
        F[OFF_DW4 + (j >> 2)*256 + h*4 + (j & 3)] = dw[q];
    }
    for (int q = tid; q < 1280; q += 512) F[OFF_CW + q] = cw[q];
    if (tid < 256) F[OFF_OW + tid] = ow[tid];
    else if (tid < 320) F[OFF_DB + tid - 256] = db[tid - 256];
    else if (tid < 384) F[OFF_CB + tid - 320] = cb[tid - 320];
    else if (tid < 388) F[OFF_OB + tid - 384] = ob[tid - 384];
    for (int q = tid; q < 320; q += 512)
        F[OFF_WIN + q] = g_window[(size_t)(g0 + q/20)*20 + q%20];
    __syncthreads();

    const int w = tid >> 5, lane = tid & 31;
    const int g = g0 + w, b = g >> 12, n = g & 4095;
    const int c0 = lane, c1 = lane + 32;

    float cv0 = F[OFF_CB + c0], cv1 = F[OFF_CB + c1];
#pragma unroll
    for (int k = 0; k < 20; k++) {
        float wk = F[OFF_WIN + w*20 + k];
        cv0 = fmaf(wk, F[OFF_CW + k*64 + c0], cv0);
        cv1 = fmaf(wk, F[OFF_CW + k*64 + c1], cv1);
    }
    float ss0 = 0.f, ss1 = 0.f;
#pragma unroll
    for (int e = 0; e < 3; e++) {
        size_t o0 = (size_t)(e*2 + b)*NH + (size_t)n*64;
        const float* pr = g_pre + (size_t)e*(8192*64) + (size_t)g*64;
        float p0 = (g_part[o0 + c0] + g_part[(size_t)6*NH + o0 + c0]
                  + g_part[(size_t)12*NH + o0 + c0]) * INV_ASCALE + pr[c0];
        float p1 = (g_part[o0 + c1] + g_part[(size_t)6*NH + o0 + c1]
                  + g_part[(size_t)12*NH + o0 + c1]) * INV_ASCALE + pr[c1];
        ss0 += tanhf(p0); ss1 += tanhf(p1);
    }
    float mk = g_mask[n];
    F[OFF_X + w*128 + c0]      = cv0;
    F[OFF_X + w*128 + c1]      = cv1;
    F[OFF_X + w*128 + 64 + c0] = tanhf(ss0) * mk;
    F[OFF_X + w*128 + 96 + c0] = tanhf(ss1) * mk;
    __syncwarp();

    float h0 = F[OFF_DB + c0], h1 = F[OFF_DB + c1];
#pragma unroll
    for (int j4 = 0; j4 < 32; j4++) {
        float4 xx = *(float4*)&F[OFF_X + w*128 + j4*4];
        float4 wa = *(float4*)&F[OFF_DW4 + j4*256 + c0*4];
        float4 wb = *(float4*)&F[OFF_DW4 + j4*256 + c1*4];
        h0 = fmaf(xx.x, wa.x, h0); h0 = fmaf(xx.y, wa.y, h0);
        h0 = fmaf(xx.z, wa.z, h0); h0 = fmaf(xx.w, wa.w, h0);
        h1 = fmaf(xx.x, wb.x, h1); h1 = fmaf(xx.y, wb.y, h1);
        h1 = fmaf(xx.z, wb.z, h1); h1 = fmaf(xx.w, wb.w, h1);
    }
    h0 = fmaxf(h0, 0.f); h1 = fmaxf(h1, 0.f);

    float od[4];
#pragma unroll
    for (int d = 0; d < 4; d++)
        od[d] = h0*F[OFF_OW + c0*4 + d] + h1*F[OFF_OW + c1*4 + d];
#pragma unroll
    for (int off = 16; off; off >>= 1)
#pragma unroll
        for (int d = 0; d < 4; d++)
            od[d] += __shfl_xor_sync(0xffffffffu, od[d], off);

    float nvl = 0.f;
    if (lane < 4) nvl = F[OFF_WIN + w*20 + 16 + lane] + tanhf(od[lane] + F[OFF_OB + lane]);
    float old4 = (lane < 16) ? F[OFF_WIN + w*20 + 4 + lane] : 0.f;
    float nvs  = __shfl_sync(0xffffffffu, nvl, lane & 3);
    float newv = (lane < 16) ? old4 : nvs;
    __syncwarp();
    if (lane < 20) {
        F[OFF_WIN + w*20 + lane] = newv;
        g_window[(size_t)g*20 + lane] = newv;
    }
    if (lane < 4)
        outp[(((size_t)b*PSTEPS + step)*4096 + n)*4 + lane] = nvl;
    __syncthreads();

    if (tid < 384) {
        int mt = tid >> 6, h = tid & 63;
        float bias = g_bAll[tid];
        for (int i = 0; i < 16; i++) {
            float a = bias;
#pragma unroll
            for (int k = 0; k < 20; k++)
                a = fmaf(F[OFF_WIN + i*20 + k], g_cwAll[(mt*20 + k)*64 + h], a);
            if (mt < 3) {
                __nv_fp8_e4m3 f8(a);
                ztb[(mt*64 + h)*16 + i] = *(uint8_t*)&f8;
            } else {
                F[OFF_PRE + i*192 + (mt - 3)*64 + h] = a;
            }
        }
    }
    __syncthreads();

    const int bb = g0 >> 12, n0v = g0 & 4095;
    for (int q = tid; q < 192; q += 512) {
        int mt = q >> 6, h = q & 63;
        *(uint4*)(g_Ztf8 + (size_t)(mt*128 + bb*64 + h)*4096 + n0v) =
            *(uint4*)(ztb + q*16);
    }
    for (int q = lane; q < 192; q += 32)
        g_pre[(size_t)(q >> 6)*(8192*64) + (size_t)g*64 + (q & 63)] =
            F[OFF_PRE + w*192 + q];
}

// ---------------------------------------------------------------------------
extern "C" void kernel_launch(void* const* d_in, const int* in_sizes, int n_in,
                              void* d_out, int out_size) {
    const float* ts   = (const float*)d_in[0];
    const float* adjs = (const float*)d_in[1];
    const float* cw   = (const float*)d_in[2];
    const float* cb   = (const float*)d_in[3];
    const float* w1   = (const float*)d_in[4];
    const float* w2   = (const float*)d_in[5];
    const float* encb = (const float*)d_in[6];
    const float* dw   = (const float*)d_in[7];
    const float* db   = (const float*)d_in[8];
    const float* ow   = (const float*)d_in[9];
    const float* ob   = (const float*)d_in[10];
    float* outp = (float*)d_out;

    cudaFuncSetAttribute(k_bigwmma, cudaFuncAttributeMaxDynamicSharedMemorySize, DSM_BYTES);
    cudaFuncSetAttribute(k_decpre,  cudaFuncAttributeMaxDynamicSharedMemorySize, DEC_SMEM_BYTES);

    // Launch order: 4th launch (ncu capture point) = k_bigwmma.
    k_setup_a<<<24576, 256>>>(adjs);                              // 1
    k_setup_b<<<688, 256>>>(ts, adjs, cw, cb, w1, w2, encb);      // 2
    k_zpre2<<<128, 256>>>();                                      // 3
    for (int p = 0; p < PSTEPS; p++) {
        k_bigwmma<<<dim3(32, 3, 3), 256, DSM_BYTES>>>();          // 4 <- profiled
        k_decpre<<<512, 512, DEC_SMEM_BYTES>>>(dw, db, ow, ob, cw, cb, outp, p);
    }
}